// round 5
// baseline (speedup 1.0000x reference)
#include <cuda_runtime.h>
#include <math.h>

#define NUM_USERS 60000
#define NUM_ITEMS 40000
#define NUM_NODES 100000
#define EMB 64
#define HID 32
#define N_EDGES 1600000
#define BATCH 16384

#define SCAN_BLK 1024
#define NB ((NUM_NODES + SCAN_BLK - 1) / SCAN_BLK)   // 98

// ---------------- device scratch (allocation-free rule) ----------------
__device__ __align__(16) float g_h1[NUM_NODES * HID];   // lin1 output
__device__ __align__(16) float g_y[NUM_NODES * HID];    // relu(agg1)
__device__ int   g_counts[NUM_NODES];                   // degree hist / cursor
__device__ int   g_row_ptr[NUM_NODES + 1];
__device__ int   g_block_sums[NB];
__device__ __align__(8) int2 g_epk[N_EDGES];            // (col, val-bits), CSR order

// ---------------------------------------------------------------------------
// lin1: h1[n][j] = feat[n].W1[j] + b1[j]. Weights in registers, activations
// broadcast by shuffle.
__global__ void lin1_kernel(const float* __restrict__ uemb,
                            const float* __restrict__ iemb,
                            const float* __restrict__ W,
                            const float* __restrict__ b) {
    int lane = threadIdx.x & 31;
    float w[EMB];
#pragma unroll
    for (int k = 0; k < EMB; k++) w[k] = __ldg(&W[lane * EMB + k]);
    float bias = __ldg(&b[lane]);

    int warp   = blockIdx.x * (blockDim.x >> 5) + (threadIdx.x >> 5);
    int nwarps = gridDim.x * (blockDim.x >> 5);

    for (int node = warp; node < NUM_NODES; node += nwarps) {
        const float* feat = (node < NUM_USERS)
            ? uemb + (size_t)node * EMB
            : iemb + (size_t)(node - NUM_USERS) * EMB;
        float x0 = __ldg(&feat[lane]);
        float x1 = __ldg(&feat[lane + 32]);
        float acc = bias;
#pragma unroll
        for (int k = 0; k < 32; k++) {
            acc += __shfl_sync(0xffffffffu, x0, k) * w[k];
            acc += __shfl_sync(0xffffffffu, x1, k) * w[k + 32];
        }
        g_h1[(size_t)node * HID + lane] = acc;
    }
}

// ---------------------------------------------------------------------------
// CSR build
__global__ void zero_counts_kernel() {
    int i = blockIdx.x * blockDim.x + threadIdx.x;
    if (i < NUM_NODES) g_counts[i] = 0;
}

__global__ void hist_kernel(const int* __restrict__ rows) {
    int e = blockIdx.x * blockDim.x + threadIdx.x;
    if (e < N_EDGES) atomicAdd(&g_counts[rows[e]], 1);
}

__global__ void scan1_kernel() {
    __shared__ int sh[SCAN_BLK];
    int tid = threadIdx.x;
    int i = blockIdx.x * SCAN_BLK + tid;
    int v = (i < NUM_NODES) ? g_counts[i] : 0;
    sh[tid] = v;
    __syncthreads();
#pragma unroll
    for (int off = 1; off < SCAN_BLK; off <<= 1) {
        int t = (tid >= off) ? sh[tid - off] : 0;
        __syncthreads();
        sh[tid] += t;
        __syncthreads();
    }
    if (i < NUM_NODES) g_row_ptr[i] = sh[tid] - v;      // exclusive
    if (tid == SCAN_BLK - 1) g_block_sums[blockIdx.x] = sh[tid];
}

__global__ void scan2_kernel() {
    __shared__ int sh[128];
    int tid = threadIdx.x;
    int v = (tid < NB) ? g_block_sums[tid] : 0;
    sh[tid] = v;
    __syncthreads();
#pragma unroll
    for (int off = 1; off < 128; off <<= 1) {
        int t = (tid >= off) ? sh[tid - off] : 0;
        __syncthreads();
        sh[tid] += t;
        __syncthreads();
    }
    if (tid < NB) g_block_sums[tid] = sh[tid] - v;      // exclusive
}

__global__ void scan3_kernel() {
    int i = blockIdx.x * blockDim.x + threadIdx.x;
    if (i < NUM_NODES) {
        int rp = g_row_ptr[i] + g_block_sums[i / SCAN_BLK];
        g_row_ptr[i] = rp;
        g_counts[i]  = rp;          // cursor for permute
    }
    if (i == 0) g_row_ptr[NUM_NODES] = N_EDGES;
}

__global__ void permute_kernel(const int* __restrict__ rows,
                               const int* __restrict__ cols,
                               const float* __restrict__ vals) {
    int e = blockIdx.x * blockDim.x + threadIdx.x;
    if (e >= N_EDGES) return;
    int r = rows[e];
    int pos = atomicAdd(&g_counts[r], 1);
    g_epk[pos] = make_int2(cols[e], __float_as_int(vals[e]));
}

// ---------------------------------------------------------------------------
// SpMM layer 1: y[r] = relu( sum_j vals_j * h1[col_j] ).  Warp/row, lane=feat.
// Edge meta loaded cooperatively (one coalesced int2 per lane per 32-chunk),
// broadcast by shfl.idx; feature gathers are independent -> high MLP.
__global__ void spmm1_kernel() {
    int lane = threadIdx.x & 31;
    int warp   = blockIdx.x * (blockDim.x >> 5) + (threadIdx.x >> 5);
    int nwarps = gridDim.x * (blockDim.x >> 5);

    for (int r = warp; r < NUM_NODES; r += nwarps) {
        int jb = g_row_ptr[r], je = g_row_ptr[r + 1];
        float acc = 0.f;
        for (int j0 = jb; j0 < je; j0 += 32) {
            int idx = j0 + lane;
            int2 cv = g_epk[idx < je ? idx : (je - 1)];
            int n = je - j0; if (n > 32) n = 32;
#pragma unroll 8
            for (int j = 0; j < n; j++) {
                int   c = __shfl_sync(0xffffffffu, cv.x, j);
                float v = __int_as_float(__shfl_sync(0xffffffffu, cv.y, j));
                acc += v * g_h1[(size_t)c * HID + lane];
            }
        }
        g_y[(size_t)r * HID + lane] = fmaxf(acc, 0.f);
    }
}

// ---------------------------------------------------------------------------
// SpMM layer 2 with post-aggregation linear (linearity of segment_sum):
//   agg[r] = sum_j v_j * y[col_j]   (32-dim gather)
//   s[r]   = sum_j v_j
//   out[r][o] = relu( agg[r].W2[o] + s[r]*b2[o] ),  o = 0..63
// Epilogue done in registers with shuffles; writes straight to d_out.
__global__ void spmm2_kernel(const float* __restrict__ W2,
                             const float* __restrict__ b2,
                             float* __restrict__ out_h2) {
    int lane = threadIdx.x & 31;
    float w0[HID], w1[HID];
#pragma unroll
    for (int k = 0; k < HID; k++) {
        w0[k] = __ldg(&W2[lane * HID + k]);
        w1[k] = __ldg(&W2[(lane + 32) * HID + k]);
    }
    float b0 = __ldg(&b2[lane]);
    float b1 = __ldg(&b2[lane + 32]);

    int warp   = blockIdx.x * (blockDim.x >> 5) + (threadIdx.x >> 5);
    int nwarps = gridDim.x * (blockDim.x >> 5);

    for (int r = warp; r < NUM_NODES; r += nwarps) {
        int jb = g_row_ptr[r], je = g_row_ptr[r + 1];
        float acc = 0.f, s = 0.f;
        for (int j0 = jb; j0 < je; j0 += 32) {
            int idx = j0 + lane;
            int2 cv = g_epk[idx < je ? idx : (je - 1)];
            int n = je - j0; if (n > 32) n = 32;
#pragma unroll 8
            for (int j = 0; j < n; j++) {
                int   c = __shfl_sync(0xffffffffu, cv.x, j);
                float v = __int_as_float(__shfl_sync(0xffffffffu, cv.y, j));
                acc += v * g_y[(size_t)c * HID + lane];
                s   += v;
            }
        }
        float o0 = s * b0, o1 = s * b1;
#pragma unroll
        for (int k = 0; k < 32; k++) {
            float xk = __shfl_sync(0xffffffffu, acc, k);
            o0 += xk * w0[k];
            o1 += xk * w1[k];
        }
        out_h2[(size_t)r * EMB + lane]      = fmaxf(o0, 0.f);
        out_h2[(size_t)r * EMB + lane + 32] = fmaxf(o1, 0.f);
    }
}

// ---------------------------------------------------------------------------
// prediction MLP. warp per batch sample; lane = hidden unit
__global__ void predict_kernel(const int* __restrict__ uid,
                               const int* __restrict__ iid,
                               const float* __restrict__ h2,
                               const float* __restrict__ p1w,
                               const float* __restrict__ p1b,
                               const float* __restrict__ p2w,
                               const float* __restrict__ p2b,
                               float* __restrict__ scores) {
    int lane = threadIdx.x & 31;
    float w[2 * EMB];
#pragma unroll
    for (int k = 0; k < 2 * EMB; k++) w[k] = __ldg(&p1w[lane * 2 * EMB + k]);
    float bias = __ldg(&p1b[lane]);
    float w2   = __ldg(&p2w[lane]);
    float b2v  = __ldg(&p2b[0]);

    int warp   = blockIdx.x * (blockDim.x >> 5) + (threadIdx.x >> 5);
    int nwarps = gridDim.x * (blockDim.x >> 5);

    for (int s = warp; s < BATCH; s += nwarps) {
        int u  = __ldg(&uid[s]);
        int it = __ldg(&iid[s]);
        const float* bu = h2 + (size_t)u * EMB;
        const float* bi = h2 + (size_t)(NUM_USERS + it) * EMB;
        float x0 = bu[lane], x1 = bu[lane + 32];
        float x2 = bi[lane], x3 = bi[lane + 32];
        float acc = bias;
#pragma unroll
        for (int k = 0; k < 32; k++) {
            acc += __shfl_sync(0xffffffffu, x0, k) * w[k];
            acc += __shfl_sync(0xffffffffu, x1, k) * w[k + 32];
            acc += __shfl_sync(0xffffffffu, x2, k) * w[k + 64];
            acc += __shfl_sync(0xffffffffu, x3, k) * w[k + 96];
        }
        float z = fmaxf(acc, 0.f) * w2;
#pragma unroll
        for (int o = 16; o > 0; o >>= 1)
            z += __shfl_xor_sync(0xffffffffu, z, o);
        if (lane == 0)
            scores[s] = 1.f / (1.f + expf(-(z + b2v)));
    }
}

// ---------------------------------------------------------------------------
extern "C" void kernel_launch(void* const* d_in, const int* in_sizes, int n_in,
                              void* d_out, int out_size) {
    const int*   user_ids = (const int*)d_in[0];
    const int*   item_ids = (const int*)d_in[1];
    const int*   adj_rows = (const int*)d_in[2];
    const int*   adj_cols = (const int*)d_in[3];
    const float* adj_vals = (const float*)d_in[4];
    const float* uemb     = (const float*)d_in[5];
    const float* iemb     = (const float*)d_in[6];
    const float* gc1w     = (const float*)d_in[7];
    const float* gc1b     = (const float*)d_in[8];
    const float* gc2w     = (const float*)d_in[9];
    const float* gc2b     = (const float*)d_in[10];
    const float* p1w      = (const float*)d_in[11];
    const float* p1b      = (const float*)d_in[12];
    const float* p2w      = (const float*)d_in[13];
    const float* p2b      = (const float*)d_in[14];

    float* out    = (float*)d_out;
    float* out_h2 = out + BATCH;   // [NUM_NODES*EMB] = concat(user_emb, item_emb)

    const int TB = 256;

    // lin1 (independent of CSR build)
    lin1_kernel<<<296, TB>>>(uemb, iemb, gc1w, gc1b);

    // ---- CSR build ----
    zero_counts_kernel<<<(NUM_NODES + TB - 1) / TB, TB>>>();
    hist_kernel<<<(N_EDGES + TB - 1) / TB, TB>>>(adj_rows);
    scan1_kernel<<<NB, SCAN_BLK>>>();
    scan2_kernel<<<1, 128>>>();
    scan3_kernel<<<(NUM_NODES + TB - 1) / TB, TB>>>();
    permute_kernel<<<(N_EDGES + TB - 1) / TB, TB>>>(adj_rows, adj_cols, adj_vals);

    // ---- layer 1 aggregate (+ fused ReLU) ----
    spmm1_kernel<<<592, TB>>>();

    // ---- layer 2 aggregate (32-dim) + fused lin2 + ReLU -> d_out ----
    spmm2_kernel<<<592, TB>>>(gc2w, gc2b, out_h2);

    // ---- prediction head ----
    predict_kernel<<<148, TB>>>(user_ids, item_ids, out_h2,
                                p1w, p1b, p2w, p2b, out);
}

// round 6
// speedup vs baseline: 1.2050x; 1.2050x over previous
#include <cuda_runtime.h>
#include <math.h>

#define NUM_USERS 60000
#define NUM_ITEMS 40000
#define NUM_NODES 100000
#define EMB 64
#define HID 32
#define N_EDGES 1600000
#define BATCH 16384

#define SCAN_BLK 1024
#define NB ((NUM_NODES + SCAN_BLK - 1) / SCAN_BLK)   // 98

// ---------------- device scratch (allocation-free rule) ----------------
__device__ __align__(16) float g_h1[NUM_NODES * HID];   // lin1 output (32-dim)
__device__ __align__(16) float g_y[NUM_NODES * HID];    // relu(agg1)  (32-dim)
__device__ int   g_counts[NUM_NODES];                   // degree hist / cursor
__device__ int   g_row_ptr[NUM_NODES + 1];
__device__ int   g_block_sums[NB];
__device__ __align__(8) int2 g_epk[N_EDGES];            // (col, val-bits), CSR order

// ---------------------------------------------------------------------------
// lin1: h1[n][j] = feat[n].W1[j] + b1[j]. Weights in registers, activations
// broadcast by shuffle (this kernel measured fast in R4; unchanged).
__global__ void lin1_kernel(const float* __restrict__ uemb,
                            const float* __restrict__ iemb,
                            const float* __restrict__ W,
                            const float* __restrict__ b) {
    int lane = threadIdx.x & 31;
    float w[EMB];
#pragma unroll
    for (int k = 0; k < EMB; k++) w[k] = __ldg(&W[lane * EMB + k]);
    float bias = __ldg(&b[lane]);

    int warp   = blockIdx.x * (blockDim.x >> 5) + (threadIdx.x >> 5);
    int nwarps = gridDim.x * (blockDim.x >> 5);

    for (int node = warp; node < NUM_NODES; node += nwarps) {
        const float* feat = (node < NUM_USERS)
            ? uemb + (size_t)node * EMB
            : iemb + (size_t)(node - NUM_USERS) * EMB;
        float x0 = __ldg(&feat[lane]);
        float x1 = __ldg(&feat[lane + 32]);
        float acc = bias;
#pragma unroll
        for (int k = 0; k < 32; k++) {
            acc += __shfl_sync(0xffffffffu, x0, k) * w[k];
            acc += __shfl_sync(0xffffffffu, x1, k) * w[k + 32];
        }
        g_h1[(size_t)node * HID + lane] = acc;
    }
}

// ---------------------------------------------------------------------------
// CSR build
__global__ void zero_counts_kernel() {
    int i = blockIdx.x * blockDim.x + threadIdx.x;
    if (i < NUM_NODES) g_counts[i] = 0;
}

__global__ void hist_kernel(const int* __restrict__ rows) {
    int e = blockIdx.x * blockDim.x + threadIdx.x;
    if (e < N_EDGES) atomicAdd(&g_counts[rows[e]], 1);
}

__global__ void scan1_kernel() {
    __shared__ int sh[SCAN_BLK];
    int tid = threadIdx.x;
    int i = blockIdx.x * SCAN_BLK + tid;
    int v = (i < NUM_NODES) ? g_counts[i] : 0;
    sh[tid] = v;
    __syncthreads();
#pragma unroll
    for (int off = 1; off < SCAN_BLK; off <<= 1) {
        int t = (tid >= off) ? sh[tid - off] : 0;
        __syncthreads();
        sh[tid] += t;
        __syncthreads();
    }
    if (i < NUM_NODES) g_row_ptr[i] = sh[tid] - v;      // exclusive
    if (tid == SCAN_BLK - 1) g_block_sums[blockIdx.x] = sh[tid];
}

__global__ void scan2_kernel() {
    __shared__ int sh[128];
    int tid = threadIdx.x;
    int v = (tid < NB) ? g_block_sums[tid] : 0;
    sh[tid] = v;
    __syncthreads();
#pragma unroll
    for (int off = 1; off < 128; off <<= 1) {
        int t = (tid >= off) ? sh[tid - off] : 0;
        __syncthreads();
        sh[tid] += t;
        __syncthreads();
    }
    if (tid < NB) g_block_sums[tid] = sh[tid] - v;      // exclusive
}

__global__ void scan3_kernel() {
    int i = blockIdx.x * blockDim.x + threadIdx.x;
    if (i < NUM_NODES) {
        int rp = g_row_ptr[i] + g_block_sums[i / SCAN_BLK];
        g_row_ptr[i] = rp;
        g_counts[i]  = rp;          // cursor for permute
    }
    if (i == 0) g_row_ptr[NUM_NODES] = N_EDGES;
}

__global__ void permute_kernel(const int* __restrict__ rows,
                               const int* __restrict__ cols,
                               const float* __restrict__ vals) {
    int e = blockIdx.x * blockDim.x + threadIdx.x;
    if (e >= N_EDGES) return;
    int r = rows[e];
    int pos = atomicAdd(&g_counts[r], 1);
    g_epk[pos] = make_int2(cols[e], __float_as_int(vals[e]));
}

// ---------------------------------------------------------------------------
// SpMM layer 1: y[r] = relu( sum_j v_j * h1[col_j] ).
// Warp handles 4 edges/iteration: lane = (g,f), g=lane>>3 edge subgroup,
// f=lane&7 float4 feature chunk. Gather is LDG.128 on aligned 128B rows.
__global__ void spmm1_kernel() {
    int lane = threadIdx.x & 31;
    int g = lane >> 3;
    int f = lane & 7;
    int warp   = blockIdx.x * (blockDim.x >> 5) + (threadIdx.x >> 5);
    int nwarps = gridDim.x * (blockDim.x >> 5);
    const float4* tbl = (const float4*)g_h1;

    for (int r = warp; r < NUM_NODES; r += nwarps) {
        int jb = g_row_ptr[r], je = g_row_ptr[r + 1];
        float4 acc = make_float4(0.f, 0.f, 0.f, 0.f);
#pragma unroll 4
        for (int j0 = jb; j0 < je; j0 += 4) {
            int j = j0 + g;
            bool act = (j < je);
            int2 cv = g_epk[act ? j : (je - 1)];
            float v = act ? __int_as_float(cv.y) : 0.f;
            float4 h = tbl[(size_t)cv.x * 8 + f];
            acc.x += v * h.x;
            acc.y += v * h.y;
            acc.z += v * h.z;
            acc.w += v * h.w;
        }
        // reduce across the 4 edge subgroups (lanes f, f+8, f+16, f+24)
#pragma unroll
        for (int o = 8; o <= 16; o <<= 1) {
            acc.x += __shfl_xor_sync(0xffffffffu, acc.x, o);
            acc.y += __shfl_xor_sync(0xffffffffu, acc.y, o);
            acc.z += __shfl_xor_sync(0xffffffffu, acc.z, o);
            acc.w += __shfl_xor_sync(0xffffffffu, acc.w, o);
        }
        if (g == 0) {
            float4 yv = make_float4(fmaxf(acc.x, 0.f), fmaxf(acc.y, 0.f),
                                    fmaxf(acc.z, 0.f), fmaxf(acc.w, 0.f));
            ((float4*)g_y)[(size_t)r * 8 + f] = yv;
        }
    }
}

// ---------------------------------------------------------------------------
// SpMM layer 2 with post-aggregation linear (linearity of segment_sum):
//   aggy[r] = sum_j v_j * y[col_j]  (32-dim),  s[r] = sum_j v_j
//   out[r][o] = relu( aggy[r].W2[o] + s[r]*b2[o] ), o=0..63  -> d_out
__global__ void spmm2_kernel(const float* __restrict__ W2,
                             const float* __restrict__ b2,
                             float* __restrict__ out_h2) {
    int lane = threadIdx.x & 31;
    int g = lane >> 3;
    int f = lane & 7;
    float w0[HID], w1[HID];
#pragma unroll
    for (int k = 0; k < HID; k++) {
        w0[k] = __ldg(&W2[lane * HID + k]);
        w1[k] = __ldg(&W2[(lane + 32) * HID + k]);
    }
    float b0 = __ldg(&b2[lane]);
    float b1 = __ldg(&b2[lane + 32]);

    int warp   = blockIdx.x * (blockDim.x >> 5) + (threadIdx.x >> 5);
    int nwarps = gridDim.x * (blockDim.x >> 5);
    const float4* tbl = (const float4*)g_y;

    for (int r = warp; r < NUM_NODES; r += nwarps) {
        int jb = g_row_ptr[r], je = g_row_ptr[r + 1];
        float4 acc = make_float4(0.f, 0.f, 0.f, 0.f);
        float s = 0.f;
#pragma unroll 4
        for (int j0 = jb; j0 < je; j0 += 4) {
            int j = j0 + g;
            bool act = (j < je);
            int2 cv = g_epk[act ? j : (je - 1)];
            float v = act ? __int_as_float(cv.y) : 0.f;
            float4 h = tbl[(size_t)cv.x * 8 + f];
            acc.x += v * h.x;
            acc.y += v * h.y;
            acc.z += v * h.z;
            acc.w += v * h.w;
            s += v;
        }
        // s was accumulated once per f within each group; reduce across groups
        // (lanes with same f at xor 8/16 are the other 3 groups)
#pragma unroll
        for (int o = 8; o <= 16; o <<= 1) {
            acc.x += __shfl_xor_sync(0xffffffffu, acc.x, o);
            acc.y += __shfl_xor_sync(0xffffffffu, acc.y, o);
            acc.z += __shfl_xor_sync(0xffffffffu, acc.z, o);
            acc.w += __shfl_xor_sync(0xffffffffu, acc.w, o);
            s     += __shfl_xor_sync(0xffffffffu, s, o);
        }
        // every lane now holds reduced acc for its f; lane k>>2 supplies
        // feature k (component k&3)
        float xs0 = acc.x, xs1 = acc.y, xs2 = acc.z, xs3 = acc.w;
        float o0 = s * b0, o1 = s * b1;
#pragma unroll
        for (int k = 0; k < 32; k++) {
            int src = k >> 2;
            float xk;
            switch (k & 3) {
                case 0: xk = __shfl_sync(0xffffffffu, xs0, src); break;
                case 1: xk = __shfl_sync(0xffffffffu, xs1, src); break;
                case 2: xk = __shfl_sync(0xffffffffu, xs2, src); break;
                default: xk = __shfl_sync(0xffffffffu, xs3, src); break;
            }
            o0 += xk * w0[k];
            o1 += xk * w1[k];
        }
        out_h2[(size_t)r * EMB + lane]      = fmaxf(o0, 0.f);
        out_h2[(size_t)r * EMB + lane + 32] = fmaxf(o1, 0.f);
    }
}

// ---------------------------------------------------------------------------
// prediction MLP. warp per batch sample; lane = hidden unit
__global__ void predict_kernel(const int* __restrict__ uid,
                               const int* __restrict__ iid,
                               const float* __restrict__ h2,
                               const float* __restrict__ p1w,
                               const float* __restrict__ p1b,
                               const float* __restrict__ p2w,
                               const float* __restrict__ p2b,
                               float* __restrict__ scores) {
    int lane = threadIdx.x & 31;
    float w[2 * EMB];
#pragma unroll
    for (int k = 0; k < 2 * EMB; k++) w[k] = __ldg(&p1w[lane * 2 * EMB + k]);
    float bias = __ldg(&p1b[lane]);
    float w2   = __ldg(&p2w[lane]);
    float b2v  = __ldg(&p2b[0]);

    int warp   = blockIdx.x * (blockDim.x >> 5) + (threadIdx.x >> 5);
    int nwarps = gridDim.x * (blockDim.x >> 5);

    for (int s = warp; s < BATCH; s += nwarps) {
        int u  = __ldg(&uid[s]);
        int it = __ldg(&iid[s]);
        const float* bu = h2 + (size_t)u * EMB;
        const float* bi = h2 + (size_t)(NUM_USERS + it) * EMB;
        float x0 = bu[lane], x1 = bu[lane + 32];
        float x2 = bi[lane], x3 = bi[lane + 32];
        float acc = bias;
#pragma unroll
        for (int k = 0; k < 32; k++) {
            acc += __shfl_sync(0xffffffffu, x0, k) * w[k];
            acc += __shfl_sync(0xffffffffu, x1, k) * w[k + 32];
            acc += __shfl_sync(0xffffffffu, x2, k) * w[k + 64];
            acc += __shfl_sync(0xffffffffu, x3, k) * w[k + 96];
        }
        float z = fmaxf(acc, 0.f) * w2;
#pragma unroll
        for (int o = 16; o > 0; o >>= 1)
            z += __shfl_xor_sync(0xffffffffu, z, o);
        if (lane == 0)
            scores[s] = 1.f / (1.f + expf(-(z + b2v)));
    }
}

// ---------------------------------------------------------------------------
extern "C" void kernel_launch(void* const* d_in, const int* in_sizes, int n_in,
                              void* d_out, int out_size) {
    const int*   user_ids = (const int*)d_in[0];
    const int*   item_ids = (const int*)d_in[1];
    const int*   adj_rows = (const int*)d_in[2];
    const int*   adj_cols = (const int*)d_in[3];
    const float* adj_vals = (const float*)d_in[4];
    const float* uemb     = (const float*)d_in[5];
    const float* iemb     = (const float*)d_in[6];
    const float* gc1w     = (const float*)d_in[7];
    const float* gc1b     = (const float*)d_in[8];
    const float* gc2w     = (const float*)d_in[9];
    const float* gc2b     = (const float*)d_in[10];
    const float* p1w      = (const float*)d_in[11];
    const float* p1b      = (const float*)d_in[12];
    const float* p2w      = (const float*)d_in[13];
    const float* p2b      = (const float*)d_in[14];

    float* out    = (float*)d_out;
    float* out_h2 = out + BATCH;   // [NUM_NODES*EMB] = concat(user_emb, item_emb)

    const int TB = 256;

    // lin1 (independent of CSR build)
    lin1_kernel<<<296, TB>>>(uemb, iemb, gc1w, gc1b);

    // ---- CSR build ----
    zero_counts_kernel<<<(NUM_NODES + TB - 1) / TB, TB>>>();
    hist_kernel<<<(N_EDGES + TB - 1) / TB, TB>>>(adj_rows);
    scan1_kernel<<<NB, SCAN_BLK>>>();
    scan2_kernel<<<1, 128>>>();
    scan3_kernel<<<(NUM_NODES + TB - 1) / TB, TB>>>();
    permute_kernel<<<(N_EDGES + TB - 1) / TB, TB>>>(adj_rows, adj_cols, adj_vals);

    // ---- layer 1 aggregate (+ fused ReLU) ----
    spmm1_kernel<<<592, TB>>>();

    // ---- layer 2 aggregate (32-dim) + fused lin2 + ReLU -> d_out ----
    spmm2_kernel<<<592, TB>>>(gc2w, gc2b, out_h2);

    // ---- prediction head ----
    predict_kernel<<<148, TB>>>(user_ids, item_ids, out_h2,
                                p1w, p1b, p2w, p2b, out);
}

// round 7
// speedup vs baseline: 1.3200x; 1.0954x over previous
#include <cuda_runtime.h>
#include <math.h>

#define NUM_USERS 60000
#define NUM_ITEMS 40000
#define NUM_NODES 100000
#define EMB 64
#define HID 32
#define N_EDGES 1600000
#define BATCH 16384

#define SCAN_BLK 1024
#define NB ((NUM_NODES + SCAN_BLK - 1) / SCAN_BLK)   // 98

#define ST_AGG  (1 << 30)
#define ST_INCL (2 << 30)
#define ST_VAL  0x3FFFFFFF

// ---------------- device scratch (allocation-free rule) ----------------
__device__ __align__(16) float g_h1[NUM_NODES * HID];   // lin1 output (32-dim)
__device__ __align__(16) float g_y[NUM_NODES * HID];    // relu(agg1)  (32-dim)
__device__ int   g_counts[NUM_NODES];                   // degree hist / cursor
__device__ int   g_row_ptr[NUM_NODES + 1];
__device__ int   g_tile_state[NB];                      // lookback-scan states
__device__ __align__(8) int2 g_epk[N_EDGES];            // (col, val-bits), CSR order

// ---------------------------------------------------------------------------
// lin1: h1[n][j] = feat[n].W1[j] + b1[j]. Also zeroes g_counts / g_tile_state
// (stream order guarantees this precedes hist/scan).
__global__ void lin1_kernel(const float* __restrict__ uemb,
                            const float* __restrict__ iemb,
                            const float* __restrict__ W,
                            const float* __restrict__ b) {
    // zeroing (grid-stride; independent of the matmul below)
    int gt = blockIdx.x * blockDim.x + threadIdx.x;
    for (int i = gt; i < NUM_NODES; i += gridDim.x * blockDim.x)
        g_counts[i] = 0;
    if (gt < NB) g_tile_state[gt] = 0;

    int lane = threadIdx.x & 31;
    float w[EMB];
#pragma unroll
    for (int k = 0; k < EMB; k++) w[k] = __ldg(&W[lane * EMB + k]);
    float bias = __ldg(&b[lane]);

    int warp   = blockIdx.x * (blockDim.x >> 5) + (threadIdx.x >> 5);
    int nwarps = gridDim.x * (blockDim.x >> 5);

    for (int node = warp; node < NUM_NODES; node += nwarps) {
        const float* feat = (node < NUM_USERS)
            ? uemb + (size_t)node * EMB
            : iemb + (size_t)(node - NUM_USERS) * EMB;
        float x0 = __ldg(&feat[lane]);
        float x1 = __ldg(&feat[lane + 32]);
        float acc = bias;
#pragma unroll
        for (int k = 0; k < 32; k++) {
            acc += __shfl_sync(0xffffffffu, x0, k) * w[k];
            acc += __shfl_sync(0xffffffffu, x1, k) * w[k + 32];
        }
        g_h1[(size_t)node * HID + lane] = acc;
    }
}

// ---------------------------------------------------------------------------
__global__ void hist_kernel(const int* __restrict__ rows) {
    int e = blockIdx.x * blockDim.x + threadIdx.x;
    if (e < N_EDGES) atomicAdd(&g_counts[rows[e]], 1);
}

// ---------------------------------------------------------------------------
// Single-pass exclusive scan of g_counts -> g_row_ptr (+ cursor copy), using
// decoupled lookback. 98 blocks; every block publishes its aggregate BEFORE
// spinning on predecessors -> progress guaranteed regardless of residency.
__global__ void scan_kernel() {
    __shared__ int sh[SCAN_BLK];
    __shared__ int s_prefix;
    int tid = threadIdx.x;
    int b = blockIdx.x;
    int i = b * SCAN_BLK + tid;
    int v = (i < NUM_NODES) ? g_counts[i] : 0;
    sh[tid] = v;
    __syncthreads();
#pragma unroll
    for (int off = 1; off < SCAN_BLK; off <<= 1) {
        int t = (tid >= off) ? sh[tid - off] : 0;
        __syncthreads();
        sh[tid] += t;
        __syncthreads();
    }
    int incl = sh[tid];
    int agg = sh[SCAN_BLK - 1];

    // publish aggregate (block 0 publishes inclusive directly)
    if (tid == 0) {
        int st = ((b == 0) ? ST_INCL : ST_AGG) | agg;
        atomicExch(&g_tile_state[b], st);
        if (b == 0) s_prefix = 0;
    }

    // warp-parallel lookback
    if (b > 0 && tid < 32) {
        int running = 0;
        int idx = b - 1;
        while (true) {
            int look = idx - tid;
            int st;
            if (look >= 0) {
                do { st = atomicAdd(&g_tile_state[look], 0); } while (st == 0);
            } else {
                st = ST_INCL;   // OOB: inclusive zero
            }
            int status = st & ~ST_VAL;
            int val    = st & ST_VAL;
            unsigned mask = __ballot_sync(0xffffffffu, status == ST_INCL);
            if (mask) {
                int first = __ffs(mask) - 1;     // nearest predecessor w/ inclusive
                int contrib = (tid < first) ? val : (tid == first ? val : 0);
#pragma unroll
                for (int o = 16; o > 0; o >>= 1)
                    contrib += __shfl_xor_sync(0xffffffffu, contrib, o);
                running += contrib;
                break;
            } else {
                int contrib = val;
#pragma unroll
                for (int o = 16; o > 0; o >>= 1)
                    contrib += __shfl_xor_sync(0xffffffffu, contrib, o);
                running += contrib;
                idx -= 32;
            }
        }
        if (tid == 0) {
            atomicExch(&g_tile_state[b], ST_INCL | (running + agg));
            s_prefix = running;
        }
    }
    __syncthreads();

    int prefix = s_prefix;
    if (i < NUM_NODES) {
        int excl = prefix + incl - v;
        g_row_ptr[i] = excl;
        g_counts[i]  = excl;          // cursor for permute
    }
    if (b == NB - 1 && tid == 0) g_row_ptr[NUM_NODES] = N_EDGES;
}

// ---------------------------------------------------------------------------
__global__ void permute_kernel(const int* __restrict__ rows,
                               const int* __restrict__ cols,
                               const float* __restrict__ vals) {
    int e = blockIdx.x * blockDim.x + threadIdx.x;
    if (e >= N_EDGES) return;
    int r = rows[e];
    int pos = atomicAdd(&g_counts[r], 1);
    g_epk[pos] = make_int2(cols[e], __float_as_int(vals[e]));
}

// ---------------------------------------------------------------------------
// SpMM layer 1: y[r] = relu( sum_j v_j * h1[col_j] ).
// Warp handles 4 edges/iteration: lane=(g,f), g edge subgroup, f float4 chunk.
__global__ void spmm1_kernel() {
    int lane = threadIdx.x & 31;
    int g = lane >> 3;
    int f = lane & 7;
    int warp   = blockIdx.x * (blockDim.x >> 5) + (threadIdx.x >> 5);
    int nwarps = gridDim.x * (blockDim.x >> 5);
    const float4* tbl = (const float4*)g_h1;

    for (int r = warp; r < NUM_NODES; r += nwarps) {
        int jb = g_row_ptr[r], je = g_row_ptr[r + 1];
        float4 acc = make_float4(0.f, 0.f, 0.f, 0.f);
#pragma unroll 4
        for (int j0 = jb; j0 < je; j0 += 4) {
            int j = j0 + g;
            bool act = (j < je);
            int2 cv = g_epk[act ? j : (je - 1)];
            float v = act ? __int_as_float(cv.y) : 0.f;
            float4 h = tbl[(size_t)cv.x * 8 + f];
            acc.x += v * h.x;
            acc.y += v * h.y;
            acc.z += v * h.z;
            acc.w += v * h.w;
        }
#pragma unroll
        for (int o = 8; o <= 16; o <<= 1) {
            acc.x += __shfl_xor_sync(0xffffffffu, acc.x, o);
            acc.y += __shfl_xor_sync(0xffffffffu, acc.y, o);
            acc.z += __shfl_xor_sync(0xffffffffu, acc.z, o);
            acc.w += __shfl_xor_sync(0xffffffffu, acc.w, o);
        }
        if (g == 0) {
            float4 yv = make_float4(fmaxf(acc.x, 0.f), fmaxf(acc.y, 0.f),
                                    fmaxf(acc.z, 0.f), fmaxf(acc.w, 0.f));
            ((float4*)g_y)[(size_t)r * 8 + f] = yv;
        }
    }
}

// ---------------------------------------------------------------------------
// SpMM layer 2 + post-aggregation linear.  W2 kept in SHARED (not registers)
// so the gather loop runs at high occupancy; epilogue reads are conflict-free.
__global__ void spmm2_kernel(const float* __restrict__ W2,
                             const float* __restrict__ b2,
                             float* __restrict__ out_h2) {
    __shared__ float sW[HID][EMB];      // sW[k][o] = W2[o][k]
    int tid = threadIdx.x;
    for (int i = tid; i < EMB * HID; i += blockDim.x) {
        int o = i >> 5, k = i & 31;
        sW[k][o] = W2[i];               // W2[o*HID + k]
    }
    __syncthreads();

    int lane = tid & 31;
    int g = lane >> 3;
    int f = lane & 7;
    float b0 = __ldg(&b2[lane]);
    float b1 = __ldg(&b2[lane + 32]);

    int warp   = blockIdx.x * (blockDim.x >> 5) + (tid >> 5);
    int nwarps = gridDim.x * (blockDim.x >> 5);
    const float4* tbl = (const float4*)g_y;

    for (int r = warp; r < NUM_NODES; r += nwarps) {
        int jb = g_row_ptr[r], je = g_row_ptr[r + 1];
        float4 acc = make_float4(0.f, 0.f, 0.f, 0.f);
        float s = 0.f;
#pragma unroll 4
        for (int j0 = jb; j0 < je; j0 += 4) {
            int j = j0 + g;
            bool act = (j < je);
            int2 cv = g_epk[act ? j : (je - 1)];
            float v = act ? __int_as_float(cv.y) : 0.f;
            float4 h = tbl[(size_t)cv.x * 8 + f];
            acc.x += v * h.x;
            acc.y += v * h.y;
            acc.z += v * h.z;
            acc.w += v * h.w;
            s += v;
        }
#pragma unroll
        for (int o = 8; o <= 16; o <<= 1) {
            acc.x += __shfl_xor_sync(0xffffffffu, acc.x, o);
            acc.y += __shfl_xor_sync(0xffffffffu, acc.y, o);
            acc.z += __shfl_xor_sync(0xffffffffu, acc.z, o);
            acc.w += __shfl_xor_sync(0xffffffffu, acc.w, o);
            s     += __shfl_xor_sync(0xffffffffu, s, o);
        }
        // lane k>>2 holds reduced feature k in component k&3
        float xs0 = acc.x, xs1 = acc.y, xs2 = acc.z, xs3 = acc.w;
        float o0 = s * b0, o1 = s * b1;
#pragma unroll
        for (int k = 0; k < 32; k++) {
            int src = k >> 2;
            float xk;
            switch (k & 3) {
                case 0: xk = __shfl_sync(0xffffffffu, xs0, src); break;
                case 1: xk = __shfl_sync(0xffffffffu, xs1, src); break;
                case 2: xk = __shfl_sync(0xffffffffu, xs2, src); break;
                default: xk = __shfl_sync(0xffffffffu, xs3, src); break;
            }
            o0 += xk * sW[k][lane];
            o1 += xk * sW[k][lane + 32];
        }
        out_h2[(size_t)r * EMB + lane]      = fmaxf(o0, 0.f);
        out_h2[(size_t)r * EMB + lane + 32] = fmaxf(o1, 0.f);
    }
}

// ---------------------------------------------------------------------------
// prediction MLP. warp per batch sample; lane = hidden unit
__global__ void predict_kernel(const int* __restrict__ uid,
                               const int* __restrict__ iid,
                               const float* __restrict__ h2,
                               const float* __restrict__ p1w,
                               const float* __restrict__ p1b,
                               const float* __restrict__ p2w,
                               const float* __restrict__ p2b,
                               float* __restrict__ scores) {
    int lane = threadIdx.x & 31;
    float w[2 * EMB];
#pragma unroll
    for (int k = 0; k < 2 * EMB; k++) w[k] = __ldg(&p1w[lane * 2 * EMB + k]);
    float bias = __ldg(&p1b[lane]);
    float w2   = __ldg(&p2w[lane]);
    float b2v  = __ldg(&p2b[0]);

    int warp   = blockIdx.x * (blockDim.x >> 5) + (threadIdx.x >> 5);
    int nwarps = gridDim.x * (blockDim.x >> 5);

    for (int s = warp; s < BATCH; s += nwarps) {
        int u  = __ldg(&uid[s]);
        int it = __ldg(&iid[s]);
        const float* bu = h2 + (size_t)u * EMB;
        const float* bi = h2 + (size_t)(NUM_USERS + it) * EMB;
        float x0 = bu[lane], x1 = bu[lane + 32];
        float x2 = bi[lane], x3 = bi[lane + 32];
        float acc = bias;
#pragma unroll
        for (int k = 0; k < 32; k++) {
            acc += __shfl_sync(0xffffffffu, x0, k) * w[k];
            acc += __shfl_sync(0xffffffffu, x1, k) * w[k + 32];
            acc += __shfl_sync(0xffffffffu, x2, k) * w[k + 64];
            acc += __shfl_sync(0xffffffffu, x3, k) * w[k + 96];
        }
        float z = fmaxf(acc, 0.f) * w2;
#pragma unroll
        for (int o = 16; o > 0; o >>= 1)
            z += __shfl_xor_sync(0xffffffffu, z, o);
        if (lane == 0)
            scores[s] = 1.f / (1.f + expf(-(z + b2v)));
    }
}

// ---------------------------------------------------------------------------
extern "C" void kernel_launch(void* const* d_in, const int* in_sizes, int n_in,
                              void* d_out, int out_size) {
    const int*   user_ids = (const int*)d_in[0];
    const int*   item_ids = (const int*)d_in[1];
    const int*   adj_rows = (const int*)d_in[2];
    const int*   adj_cols = (const int*)d_in[3];
    const float* adj_vals = (const float*)d_in[4];
    const float* uemb     = (const float*)d_in[5];
    const float* iemb     = (const float*)d_in[6];
    const float* gc1w     = (const float*)d_in[7];
    const float* gc1b     = (const float*)d_in[8];
    const float* gc2w     = (const float*)d_in[9];
    const float* gc2b     = (const float*)d_in[10];
    const float* p1w      = (const float*)d_in[11];
    const float* p1b      = (const float*)d_in[12];
    const float* p2w      = (const float*)d_in[13];
    const float* p2b      = (const float*)d_in[14];

    float* out    = (float*)d_out;
    float* out_h2 = out + BATCH;   // [NUM_NODES*EMB] = concat(user_emb, item_emb)

    const int TB = 256;

    // 1: lin1 + zero counts/tile-states
    lin1_kernel<<<592, TB>>>(uemb, iemb, gc1w, gc1b);
    // 2: degree histogram
    hist_kernel<<<(N_EDGES + TB - 1) / TB, TB>>>(adj_rows);
    // 3: single-pass lookback scan -> row_ptr + cursor
    scan_kernel<<<NB, SCAN_BLK>>>();
    // 4: CSR permute
    permute_kernel<<<(N_EDGES + TB - 1) / TB, TB>>>(adj_rows, adj_cols, adj_vals);
    // 5: layer-1 aggregate + ReLU
    spmm1_kernel<<<1184, TB>>>();
    // 6: layer-2 aggregate + lin2 + ReLU -> d_out
    spmm2_kernel<<<1184, TB>>>(gc2w, gc2b, out_h2);
    // 7: prediction head
    predict_kernel<<<148, TB>>>(user_ids, item_ids, out_h2,
                                p1w, p1b, p2w, p2b, out);
}